// round 3
// baseline (speedup 1.0000x reference)
#include <cuda_runtime.h>
#include <cuda_bf16.h>
#include <math.h>

// Problem constants
#define BATCH 4
#define SEQ   2048
#define DIM   1024
#define HEADS 16
#define HDIM  64
#define ROWS  (BATCH * SEQ)   // 8192

// Scratch (device globals; no allocation allowed)
__device__ float g_Q[ROWS * DIM];
__device__ float g_K[ROWS * DIM];
__device__ float g_V[ROWS * DIM];
__device__ float g_AO[ROWS * DIM];
__device__ float g_part[16 * BATCH * DIM];
__device__ float g_mean[BATCH * DIM];

// ---------------------------------------------------------------------------
// QKV projection: C[m,n] = sum_k x[m,k] * W[n,k] + b[n]
// 128x128x16 tiles, 256 threads, 8x8 microtile, double-buffered smem
// (one __syncthreads per k-iteration). grid.z selects Q/K/V.
// ---------------------------------------------------------------------------
__global__ __launch_bounds__(256) void qkv_gemm(
    const float* __restrict__ x,
    const float* __restrict__ Wq, const float* __restrict__ bq,
    const float* __restrict__ Wk, const float* __restrict__ bk,
    const float* __restrict__ Wv, const float* __restrict__ bv)
{
    const float* W;
    const float* bias;
    float* out;
    if (blockIdx.z == 0)      { W = Wq; bias = bq; out = g_Q; }
    else if (blockIdx.z == 1) { W = Wk; bias = bk; out = g_K; }
    else                      { W = Wv; bias = bv; out = g_V; }

    __shared__ float As[2][16][128];   // [buf][k][m]
    __shared__ float Bs[2][16][128];   // [buf][k][n]

    const int tid = threadIdx.x;
    const int tx = tid & 15;
    const int ty = tid >> 4;
    const int row0 = blockIdx.y * 128;
    const int col0 = blockIdx.x * 128;

    const int lr = tid >> 2;          // 0..63
    const int lc = (tid & 3) * 4;     // k offset within 16 (float4)

    const float* xA0 = &x[(size_t)(row0 + lr) * DIM + lc];
    const float* xA1 = &x[(size_t)(row0 + lr + 64) * DIM + lc];
    const float* wB0 = &W[(size_t)(col0 + lr) * DIM + lc];
    const float* wB1 = &W[(size_t)(col0 + lr + 64) * DIM + lc];

    float acc[8][8];
#pragma unroll
    for (int i = 0; i < 8; i++)
#pragma unroll
        for (int j = 0; j < 8; j++) acc[i][j] = 0.f;

    // Prologue: load tile 0 into buffer 0
    {
        float4 a0 = *(const float4*)(xA0);
        float4 a1 = *(const float4*)(xA1);
        float4 b0 = *(const float4*)(wB0);
        float4 b1 = *(const float4*)(wB1);
        As[0][lc + 0][lr] = a0.x; As[0][lc + 1][lr] = a0.y;
        As[0][lc + 2][lr] = a0.z; As[0][lc + 3][lr] = a0.w;
        As[0][lc + 0][lr + 64] = a1.x; As[0][lc + 1][lr + 64] = a1.y;
        As[0][lc + 2][lr + 64] = a1.z; As[0][lc + 3][lr + 64] = a1.w;
        Bs[0][lc + 0][lr] = b0.x; Bs[0][lc + 1][lr] = b0.y;
        Bs[0][lc + 2][lr] = b0.z; Bs[0][lc + 3][lr] = b0.w;
        Bs[0][lc + 0][lr + 64] = b1.x; Bs[0][lc + 1][lr + 64] = b1.y;
        Bs[0][lc + 2][lr + 64] = b1.z; Bs[0][lc + 3][lr + 64] = b1.w;
    }
    __syncthreads();

    int cur = 0;
    for (int k0 = 0; k0 < DIM; k0 += 16) {
        // Issue next tile's global loads early (latency overlapped with compute)
        float4 a0, a1, b0, b1;
        const bool has_next = (k0 + 16) < DIM;
        if (has_next) {
            a0 = *(const float4*)(xA0 + k0 + 16);
            a1 = *(const float4*)(xA1 + k0 + 16);
            b0 = *(const float4*)(wB0 + k0 + 16);
            b1 = *(const float4*)(wB1 + k0 + 16);
        }

        // Compute from current buffer
#pragma unroll
        for (int kk = 0; kk < 16; kk++) {
            float4 af0 = *(float4*)&As[cur][kk][ty * 8];
            float4 af1 = *(float4*)&As[cur][kk][ty * 8 + 4];
            float4 bf0 = *(float4*)&Bs[cur][kk][tx * 8];
            float4 bf1 = *(float4*)&Bs[cur][kk][tx * 8 + 4];
            float a[8] = {af0.x, af0.y, af0.z, af0.w, af1.x, af1.y, af1.z, af1.w};
            float bb[8] = {bf0.x, bf0.y, bf0.z, bf0.w, bf1.x, bf1.y, bf1.z, bf1.w};
#pragma unroll
            for (int i = 0; i < 8; i++)
#pragma unroll
                for (int j = 0; j < 8; j++)
                    acc[i][j] = fmaf(a[i], bb[j], acc[i][j]);
        }

        // Store next tile into the other buffer; safe because all reads of
        // that buffer finished before the barrier at the end of the previous
        // iteration.
        if (has_next) {
            const int nxt = cur ^ 1;
            As[nxt][lc + 0][lr] = a0.x; As[nxt][lc + 1][lr] = a0.y;
            As[nxt][lc + 2][lr] = a0.z; As[nxt][lc + 3][lr] = a0.w;
            As[nxt][lc + 0][lr + 64] = a1.x; As[nxt][lc + 1][lr + 64] = a1.y;
            As[nxt][lc + 2][lr + 64] = a1.z; As[nxt][lc + 3][lr + 64] = a1.w;
            Bs[nxt][lc + 0][lr] = b0.x; Bs[nxt][lc + 1][lr] = b0.y;
            Bs[nxt][lc + 2][lr] = b0.z; Bs[nxt][lc + 3][lr] = b0.w;
            Bs[nxt][lc + 0][lr + 64] = b1.x; Bs[nxt][lc + 1][lr + 64] = b1.y;
            Bs[nxt][lc + 2][lr + 64] = b1.z; Bs[nxt][lc + 3][lr + 64] = b1.w;
            __syncthreads();
            cur = nxt;
        }
    }

#pragma unroll
    for (int i = 0; i < 8; i++) {
        const int r = row0 + ty * 8 + i;
#pragma unroll
        for (int j = 0; j < 8; j += 4) {
            const int c = col0 + tx * 8 + j;
            float4 v;
            v.x = acc[i][j + 0] + bias[c + 0];
            v.y = acc[i][j + 1] + bias[c + 1];
            v.z = acc[i][j + 2] + bias[c + 2];
            v.w = acc[i][j + 3] + bias[c + 3];
            *(float4*)&out[(size_t)r * DIM + c] = v;
        }
    }
}

// ---------------------------------------------------------------------------
// Flash attention: one CTA per (qtile=64, head, batch).
// Qst/Kst transposed [d][row] in SMEM; K buffer reused for P.
// ---------------------------------------------------------------------------
__global__ __launch_bounds__(256) void attn_kernel()
{
    const int qt = blockIdx.x;   // 0..31
    const int h  = blockIdx.y;   // 0..15
    const int b  = blockIdx.z;   // 0..3

    __shared__ float Qst[64][64];   // [d][i]
    __shared__ float KPs[64][64];   // Kst [d][j], then Ps [i][j]
    __shared__ float Vs[64][64];    // [j][d]

    const int tid = threadIdx.x;
    const int tx = tid & 15;
    const int ty = tid >> 4;
    const int lr = tid >> 2;         // row 0..63
    const int lq = (tid & 3) * 16;   // dim chunk start

    const size_t headOff = (size_t)b * SEQ * DIM + (size_t)h * HDIM;

    // Load Q tile transposed
    {
        const float* src = g_Q + headOff + (size_t)(qt * 64 + lr) * DIM + lq;
#pragma unroll
        for (int c = 0; c < 4; c++) {
            float4 f = *(const float4*)(src + c * 4);
            int d = lq + c * 4;
            Qst[d + 0][lr] = f.x; Qst[d + 1][lr] = f.y;
            Qst[d + 2][lr] = f.z; Qst[d + 3][lr] = f.w;
        }
    }

    float m_prev[4], lsum[4], O[4][4];
#pragma unroll
    for (int r = 0; r < 4; r++) {
        m_prev[r] = -INFINITY; lsum[r] = 0.f;
#pragma unroll
        for (int c = 0; c < 4; c++) O[r][c] = 0.f;
    }

    const float* Kbase = g_K + headOff;
    const float* Vbase = g_V + headOff;

    for (int j0 = 0; j0 < SEQ; j0 += 64) {
        __syncthreads();   // previous iter done reading KPs/Vs
        {
            const float* ks = Kbase + (size_t)(j0 + lr) * DIM + lq;
            const float* vsrc = Vbase + (size_t)(j0 + lr) * DIM + lq;
#pragma unroll
            for (int c = 0; c < 4; c++) {
                float4 f = *(const float4*)(ks + c * 4);
                int d = lq + c * 4;
                KPs[d + 0][lr] = f.x; KPs[d + 1][lr] = f.y;
                KPs[d + 2][lr] = f.z; KPs[d + 3][lr] = f.w;
            }
#pragma unroll
            for (int c = 0; c < 4; c++) {
                float4 f = *(const float4*)(vsrc + c * 4);
                *(float4*)&Vs[lr][lq + c * 4] = f;
            }
        }
        __syncthreads();

        // S = Q K^T (scaled)
        float s[4][4];
#pragma unroll
        for (int r = 0; r < 4; r++)
#pragma unroll
            for (int c = 0; c < 4; c++) s[r][c] = 0.f;
#pragma unroll
        for (int d = 0; d < 64; d++) {
            float4 qf = *(float4*)&Qst[d][ty * 4];
            float4 kf = *(float4*)&KPs[d][tx * 4];
            float qa[4] = {qf.x, qf.y, qf.z, qf.w};
            float ka[4] = {kf.x, kf.y, kf.z, kf.w};
#pragma unroll
            for (int r = 0; r < 4; r++)
#pragma unroll
                for (int c = 0; c < 4; c++)
                    s[r][c] = fmaf(qa[r], ka[c], s[r][c]);
        }
        const float scale = 0.125f;  // 1/sqrt(64)
#pragma unroll
        for (int r = 0; r < 4; r++)
#pragma unroll
            for (int c = 0; c < 4; c++) s[r][c] *= scale;

        __syncthreads();   // everyone finished reading Kst before P overwrites

        // Online softmax per row; write P into KPs
#pragma unroll
        for (int r = 0; r < 4; r++) {
            float mx = fmaxf(fmaxf(s[r][0], s[r][1]), fmaxf(s[r][2], s[r][3]));
            mx = fmaxf(mx, __shfl_xor_sync(0xffffffffu, mx, 8));
            mx = fmaxf(mx, __shfl_xor_sync(0xffffffffu, mx, 4));
            mx = fmaxf(mx, __shfl_xor_sync(0xffffffffu, mx, 2));
            mx = fmaxf(mx, __shfl_xor_sync(0xffffffffu, mx, 1));
            float mn = fmaxf(m_prev[r], mx);
            float corr = __expf(m_prev[r] - mn);
            float ps = 0.f;
#pragma unroll
            for (int c = 0; c < 4; c++) {
                s[r][c] = __expf(s[r][c] - mn);
                ps += s[r][c];
            }
            ps += __shfl_xor_sync(0xffffffffu, ps, 8);
            ps += __shfl_xor_sync(0xffffffffu, ps, 4);
            ps += __shfl_xor_sync(0xffffffffu, ps, 2);
            ps += __shfl_xor_sync(0xffffffffu, ps, 1);
            lsum[r] = lsum[r] * corr + ps;
            m_prev[r] = mn;
#pragma unroll
            for (int c = 0; c < 4; c++) O[r][c] *= corr;
            *(float4*)&KPs[ty * 4 + r][tx * 4] =
                make_float4(s[r][0], s[r][1], s[r][2], s[r][3]);
        }
        __syncthreads();

        // O += P @ V, chunked by 4 in jj: all-LDS128, 8 FFMA per LDS.
#pragma unroll 4
        for (int jj0 = 0; jj0 < 64; jj0 += 4) {
            float4 pf[4];   // P[ty*4+r][jj0..jj0+3]
#pragma unroll
            for (int r = 0; r < 4; r++)
                pf[r] = *(float4*)&KPs[ty * 4 + r][jj0];
            float4 vf[4];   // V[jj0+i][tx*4..tx*4+3]
#pragma unroll
            for (int i = 0; i < 4; i++)
                vf[i] = *(float4*)&Vs[jj0 + i][tx * 4];
#pragma unroll
            for (int r = 0; r < 4; r++) {
                float pa[4] = {pf[r].x, pf[r].y, pf[r].z, pf[r].w};
#pragma unroll
                for (int i = 0; i < 4; i++) {
                    O[r][0] = fmaf(pa[i], vf[i].x, O[r][0]);
                    O[r][1] = fmaf(pa[i], vf[i].y, O[r][1]);
                    O[r][2] = fmaf(pa[i], vf[i].z, O[r][2]);
                    O[r][3] = fmaf(pa[i], vf[i].w, O[r][3]);
                }
            }
        }
    }

    // Write normalized output tile
    float* outp = g_AO + headOff + (size_t)(qt * 64) * DIM;
#pragma unroll
    for (int r = 0; r < 4; r++) {
        float inv = 1.f / lsum[r];
        float4 v = make_float4(O[r][0] * inv, O[r][1] * inv,
                               O[r][2] * inv, O[r][3] * inv);
        *(float4*)&outp[(size_t)(ty * 4 + r) * DIM + tx * 4] = v;
    }
}

// ---------------------------------------------------------------------------
// Mean over T (split + reduce), then output projection on [B, D] only.
// ---------------------------------------------------------------------------
__global__ void mean_partial()
{
    // grid (8, 16, 4), block 128
    const int d  = blockIdx.x * 128 + threadIdx.x;
    const int tc = blockIdx.y;
    const int b  = blockIdx.z;
    const float* p = g_AO + ((size_t)(b * SEQ + tc * 128)) * DIM + d;
    float s = 0.f;
#pragma unroll 8
    for (int t = 0; t < 128; t++) s += p[(size_t)t * DIM];
    g_part[(tc * BATCH + b) * DIM + d] = s;
}

__global__ void mean_reduce()
{
    const int i = blockIdx.x * 256 + threadIdx.x;  // b*1024 + d
    float s = 0.f;
#pragma unroll
    for (int tc = 0; tc < 16; tc++) s += g_part[tc * (BATCH * DIM) + i];
    g_mean[i] = s * (1.f / (float)SEQ);
}

__global__ void out_proj(const float* __restrict__ Wo,
                         const float* __restrict__ bo,
                         float* __restrict__ out)
{
    // grid 512, block 256: one warp per output element
    const int warp = threadIdx.x >> 5;
    const int lane = threadIdx.x & 31;
    const int idx = blockIdx.x * 8 + warp;   // 0..4095
    const int b = idx >> 10;
    const int d = idx & 1023;
    const float* m = g_mean + b * DIM;
    const float* w = Wo + (size_t)d * DIM;
    float s = 0.f;
    for (int k = lane; k < DIM; k += 32) s = fmaf(m[k], w[k], s);
#pragma unroll
    for (int off = 16; off > 0; off >>= 1)
        s += __shfl_xor_sync(0xffffffffu, s, off);
    if (lane == 0) out[idx] = s + bo[d];
}

// ---------------------------------------------------------------------------
extern "C" void kernel_launch(void* const* d_in, const int* in_sizes, int n_in,
                              void* d_out, int out_size)
{
    const float* x  = (const float*)d_in[0];
    const float* Wq = (const float*)d_in[1];
    const float* bq = (const float*)d_in[2];
    const float* Wk = (const float*)d_in[3];
    const float* bk = (const float*)d_in[4];
    const float* Wv = (const float*)d_in[5];
    const float* bv = (const float*)d_in[6];
    const float* Wo = (const float*)d_in[7];
    const float* bo = (const float*)d_in[8];
    float* out = (float*)d_out;

    qkv_gemm<<<dim3(DIM / 128, ROWS / 128, 3), 256>>>(x, Wq, bq, Wk, bk, Wv, bv);
    attn_kernel<<<dim3(SEQ / 64, HEADS, BATCH), 256>>>();
    mean_partial<<<dim3(DIM / 128, 16, BATCH), 128>>>();
    mean_reduce<<<(BATCH * DIM) / 256, 256>>>();
    out_proj<<<(BATCH * DIM) / 8, 256>>>(Wo, bo, out);
}

// round 5
// speedup vs baseline: 1.2357x; 1.2357x over previous
#include <cuda_runtime.h>
#include <cuda_bf16.h>
#include <math.h>
#include <stdint.h>

// Problem constants
#define BATCH 4
#define SEQ   2048
#define DIM   1024
#define HEADS 16
#define HDIM  64
#define ROWS  (BATCH * SEQ)   // 8192

// GEMM tiling
#define BM 128
#define BN 128
#define BK 32
#define BKP 40   // padded row stride (bf16 elems): 80B -> conflict-free frag loads

// Scratch (device globals; no allocation allowed)
__device__ float g_Q[ROWS * DIM];
__device__ float g_K[ROWS * DIM];
__device__ float g_V[ROWS * DIM];
__device__ float g_AO[ROWS * DIM];
__device__ float g_part[16 * BATCH * DIM];
__device__ float g_mean[BATCH * DIM];

__device__ __nv_bfloat16 g_xhi[ROWS * DIM];
__device__ __nv_bfloat16 g_xlo[ROWS * DIM];
__device__ __nv_bfloat16 g_Whi[3 * DIM * DIM];
__device__ __nv_bfloat16 g_Wlo[3 * DIM * DIM];

// ---------------------------------------------------------------------------
// fp32 -> bf16 hi/lo split converters
// ---------------------------------------------------------------------------
__global__ void split_x(const float* __restrict__ src)
{
    const int idx = blockIdx.x * blockDim.x + threadIdx.x;  // float4 index
    float4 v = ((const float4*)src)[idx];
    __nv_bfloat16 h0 = __float2bfloat16_rn(v.x);
    __nv_bfloat16 h1 = __float2bfloat16_rn(v.y);
    __nv_bfloat16 h2 = __float2bfloat16_rn(v.z);
    __nv_bfloat16 h3 = __float2bfloat16_rn(v.w);
    __nv_bfloat16 l0 = __float2bfloat16_rn(v.x - __bfloat162float(h0));
    __nv_bfloat16 l1 = __float2bfloat16_rn(v.y - __bfloat162float(h1));
    __nv_bfloat16 l2 = __float2bfloat16_rn(v.z - __bfloat162float(h2));
    __nv_bfloat16 l3 = __float2bfloat16_rn(v.w - __bfloat162float(h3));
    ((__nv_bfloat162*)g_xhi)[idx * 2 + 0] = __halves2bfloat162(h0, h1);
    ((__nv_bfloat162*)g_xhi)[idx * 2 + 1] = __halves2bfloat162(h2, h3);
    ((__nv_bfloat162*)g_xlo)[idx * 2 + 0] = __halves2bfloat162(l0, l1);
    ((__nv_bfloat162*)g_xlo)[idx * 2 + 1] = __halves2bfloat162(l2, l3);
}

// One launch covers Wq/Wk/Wv via blockIdx.y.
__global__ void split_w(const float* __restrict__ Wq,
                        const float* __restrict__ Wk,
                        const float* __restrict__ Wv)
{
    const int z = blockIdx.y;
    const float* src = (z == 0) ? Wq : (z == 1) ? Wk : Wv;
    const int idx = blockIdx.x * blockDim.x + threadIdx.x;  // float4 index
    const size_t base2 = (size_t)z * (DIM * DIM / 2);       // bf162 offset
    float4 v = ((const float4*)src)[idx];
    __nv_bfloat16 h0 = __float2bfloat16_rn(v.x);
    __nv_bfloat16 h1 = __float2bfloat16_rn(v.y);
    __nv_bfloat16 h2 = __float2bfloat16_rn(v.z);
    __nv_bfloat16 h3 = __float2bfloat16_rn(v.w);
    __nv_bfloat16 l0 = __float2bfloat16_rn(v.x - __bfloat162float(h0));
    __nv_bfloat16 l1 = __float2bfloat16_rn(v.y - __bfloat162float(h1));
    __nv_bfloat16 l2 = __float2bfloat16_rn(v.z - __bfloat162float(h2));
    __nv_bfloat16 l3 = __float2bfloat16_rn(v.w - __bfloat162float(h3));
    ((__nv_bfloat162*)g_Whi)[base2 + idx * 2 + 0] = __halves2bfloat162(h0, h1);
    ((__nv_bfloat162*)g_Whi)[base2 + idx * 2 + 1] = __halves2bfloat162(h2, h3);
    ((__nv_bfloat162*)g_Wlo)[base2 + idx * 2 + 0] = __halves2bfloat162(l0, l1);
    ((__nv_bfloat162*)g_Wlo)[base2 + idx * 2 + 1] = __halves2bfloat162(l2, l3);
}

// ---------------------------------------------------------------------------
// QKV projection with bf16 split-precision tensor-core MMA.
// C[m,n] = sum_k x[m,k] * W[n,k] + b[n]
// 128x128x32 CTA tile, 256 threads = 8 warps (2m x 4n), warp tile 64x32.
// 3-pass split: hi*hi + hi*lo + lo*hi (fp32 accumulate).
// ---------------------------------------------------------------------------
#define MMA_BF16(d, a, b) \
    asm volatile( \
        "mma.sync.aligned.m16n8k16.row.col.f32.bf16.bf16.f32 " \
        "{%0,%1,%2,%3}, {%4,%5,%6,%7}, {%8,%9}, {%0,%1,%2,%3};\n" \
        : "+f"(d[0]), "+f"(d[1]), "+f"(d[2]), "+f"(d[3]) \
        : "r"(a[0]), "r"(a[1]), "r"(a[2]), "r"(a[3]), "r"(b[0]), "r"(b[1]))

__global__ __launch_bounds__(256) void qkv_gemm_mma(
    const float* __restrict__ bq,
    const float* __restrict__ bk,
    const float* __restrict__ bv)
{
    const int z = blockIdx.z;
    const float* bias;
    float* out;
    if (z == 0)      { bias = bq; out = g_Q; }
    else if (z == 1) { bias = bk; out = g_K; }
    else             { bias = bv; out = g_V; }

    const __nv_bfloat16* Bhi = g_Whi + (size_t)z * DIM * DIM;
    const __nv_bfloat16* Blo = g_Wlo + (size_t)z * DIM * DIM;

    __shared__ __nv_bfloat16 sAhi[BM * BKP];
    __shared__ __nv_bfloat16 sAlo[BM * BKP];
    __shared__ __nv_bfloat16 sBhi[BN * BKP];
    __shared__ __nv_bfloat16 sBlo[BN * BKP];

    const int tid = threadIdx.x;
    const int wid = tid >> 5;
    const int lane = tid & 31;
    const int warp_m = wid & 1;        // 0..1 -> 64 rows each
    const int warp_n = wid >> 1;       // 0..3 -> 32 cols each
    const int g = lane >> 2;           // group 0..7
    const int tg = (lane & 3) * 2;     // k/col pair offset

    const int row0 = blockIdx.y * BM;
    const int col0 = blockIdx.x * BN;

    // Loader mapping: each thread loads 2 rows x 8 bf16 per tile
    const int lrow = tid >> 2;             // 0..63
    const int lcol = (tid & 3) * 8;        // 0,8,16,24

    const __nv_bfloat16* gA0hi = &g_xhi[(size_t)(row0 + lrow) * DIM + lcol];
    const __nv_bfloat16* gA1hi = &g_xhi[(size_t)(row0 + lrow + 64) * DIM + lcol];
    const __nv_bfloat16* gA0lo = &g_xlo[(size_t)(row0 + lrow) * DIM + lcol];
    const __nv_bfloat16* gA1lo = &g_xlo[(size_t)(row0 + lrow + 64) * DIM + lcol];
    const __nv_bfloat16* gB0hi = &Bhi[(size_t)(col0 + lrow) * DIM + lcol];
    const __nv_bfloat16* gB1hi = &Bhi[(size_t)(col0 + lrow + 64) * DIM + lcol];
    const __nv_bfloat16* gB0lo = &Blo[(size_t)(col0 + lrow) * DIM + lcol];
    const __nv_bfloat16* gB1lo = &Blo[(size_t)(col0 + lrow + 64) * DIM + lcol];

    float acc[4][4][4];
#pragma unroll
    for (int mf = 0; mf < 4; mf++)
#pragma unroll
        for (int nf = 0; nf < 4; nf++)
#pragma unroll
            for (int i = 0; i < 4; i++) acc[mf][nf][i] = 0.f;

    uint4 pA0hi, pA1hi, pA0lo, pA1lo, pB0hi, pB1hi, pB0lo, pB1lo;

    // Prologue load (k0 = 0)
    pA0hi = *(const uint4*)(gA0hi); pA1hi = *(const uint4*)(gA1hi);
    pA0lo = *(const uint4*)(gA0lo); pA1lo = *(const uint4*)(gA1lo);
    pB0hi = *(const uint4*)(gB0hi); pB1hi = *(const uint4*)(gB1hi);
    pB0lo = *(const uint4*)(gB0lo); pB1lo = *(const uint4*)(gB1lo);

    for (int k0 = 0; k0 < DIM; k0 += BK) {
        // Store prefetched tile to smem
        *(uint4*)&sAhi[lrow * BKP + lcol] = pA0hi;
        *(uint4*)&sAhi[(lrow + 64) * BKP + lcol] = pA1hi;
        *(uint4*)&sAlo[lrow * BKP + lcol] = pA0lo;
        *(uint4*)&sAlo[(lrow + 64) * BKP + lcol] = pA1lo;
        *(uint4*)&sBhi[lrow * BKP + lcol] = pB0hi;
        *(uint4*)&sBhi[(lrow + 64) * BKP + lcol] = pB1hi;
        *(uint4*)&sBlo[lrow * BKP + lcol] = pB0lo;
        *(uint4*)&sBlo[(lrow + 64) * BKP + lcol] = pB1lo;
        __syncthreads();

        // Prefetch next k tile while computing
        if (k0 + BK < DIM) {
            const int kn = k0 + BK;
            pA0hi = *(const uint4*)(gA0hi + kn); pA1hi = *(const uint4*)(gA1hi + kn);
            pA0lo = *(const uint4*)(gA0lo + kn); pA1lo = *(const uint4*)(gA1lo + kn);
            pB0hi = *(const uint4*)(gB0hi + kn); pB1hi = *(const uint4*)(gB1hi + kn);
            pB0lo = *(const uint4*)(gB0lo + kn); pB1lo = *(const uint4*)(gB1lo + kn);
        }

#pragma unroll
        for (int ks = 0; ks < BK; ks += 16) {
            uint32_t ahi[4][4], alo[4][4], bhi[4][2], blo[4][2];
#pragma unroll
            for (int mf = 0; mf < 4; mf++) {
                const int am = warp_m * 64 + mf * 16 + g;
                ahi[mf][0] = *(const uint32_t*)&sAhi[am * BKP + ks + tg];
                ahi[mf][1] = *(const uint32_t*)&sAhi[(am + 8) * BKP + ks + tg];
                ahi[mf][2] = *(const uint32_t*)&sAhi[am * BKP + ks + 8 + tg];
                ahi[mf][3] = *(const uint32_t*)&sAhi[(am + 8) * BKP + ks + 8 + tg];
                alo[mf][0] = *(const uint32_t*)&sAlo[am * BKP + ks + tg];
                alo[mf][1] = *(const uint32_t*)&sAlo[(am + 8) * BKP + ks + tg];
                alo[mf][2] = *(const uint32_t*)&sAlo[am * BKP + ks + 8 + tg];
                alo[mf][3] = *(const uint32_t*)&sAlo[(am + 8) * BKP + ks + 8 + tg];
            }
#pragma unroll
            for (int nf = 0; nf < 4; nf++) {
                const int bn = warp_n * 32 + nf * 8 + g;
                bhi[nf][0] = *(const uint32_t*)&sBhi[bn * BKP + ks + tg];
                bhi[nf][1] = *(const uint32_t*)&sBhi[bn * BKP + ks + 8 + tg];
                blo[nf][0] = *(const uint32_t*)&sBlo[bn * BKP + ks + tg];
                blo[nf][1] = *(const uint32_t*)&sBlo[bn * BKP + ks + 8 + tg];
            }
#pragma unroll
            for (int mf = 0; mf < 4; mf++)
#pragma unroll
                for (int nf = 0; nf < 4; nf++) {
                    MMA_BF16(acc[mf][nf], ahi[mf], bhi[nf]);
                    MMA_BF16(acc[mf][nf], ahi[mf], blo[nf]);
                    MMA_BF16(acc[mf][nf], alo[mf], bhi[nf]);
                }
        }
        __syncthreads();
    }

    // Epilogue: add fp32 bias, store fp32
#pragma unroll
    for (int mf = 0; mf < 4; mf++) {
        const int r0 = row0 + warp_m * 64 + mf * 16 + g;
#pragma unroll
        for (int nf = 0; nf < 4; nf++) {
            const int c = col0 + warp_n * 32 + nf * 8 + tg;
            float2 v0 = make_float2(acc[mf][nf][0] + bias[c],
                                    acc[mf][nf][1] + bias[c + 1]);
            float2 v1 = make_float2(acc[mf][nf][2] + bias[c],
                                    acc[mf][nf][3] + bias[c + 1]);
            *(float2*)&out[(size_t)r0 * DIM + c] = v0;
            *(float2*)&out[(size_t)(r0 + 8) * DIM + c] = v1;
        }
    }
}

// ---------------------------------------------------------------------------
// Flash attention: one CTA per (qtile=64, head, batch). (unchanged, fp32)
// ---------------------------------------------------------------------------
__global__ __launch_bounds__(256) void attn_kernel()
{
    const int qt = blockIdx.x;   // 0..31
    const int h  = blockIdx.y;   // 0..15
    const int b  = blockIdx.z;   // 0..3

    __shared__ float Qst[64][64];   // [d][i]
    __shared__ float KPs[64][64];   // Kst [d][j], then Ps [i][j]
    __shared__ float Vs[64][64];    // [j][d]

    const int tid = threadIdx.x;
    const int tx = tid & 15;
    const int ty = tid >> 4;
    const int lr = tid >> 2;         // row 0..63
    const int lq = (tid & 3) * 16;   // dim chunk start

    const size_t headOff = (size_t)b * SEQ * DIM + (size_t)h * HDIM;

    // Load Q tile transposed
    {
        const float* src = g_Q + headOff + (size_t)(qt * 64 + lr) * DIM + lq;
#pragma unroll
        for (int c = 0; c < 4; c++) {
            float4 f = *(const float4*)(src + c * 4);
            int d = lq + c * 4;
            Qst[d + 0][lr] = f.x; Qst[d + 1][lr] = f.y;
            Qst[d + 2][lr] = f.z; Qst[d + 3][lr] = f.w;
        }
    }

    float m_prev[4], lsum[4], O[4][4];
#pragma unroll
    for (int r = 0; r < 4; r++) {
        m_prev[r] = -INFINITY; lsum[r] = 0.f;
#pragma unroll
        for (int c = 0; c < 4; c++) O[r][c] = 0.f;
    }

    const float* Kbase = g_K + headOff;
    const float* Vbase = g_V + headOff;

    for (int j0 = 0; j0 < SEQ; j0 += 64) {
        __syncthreads();   // previous iter done reading KPs/Vs
        {
            const float* ks = Kbase + (size_t)(j0 + lr) * DIM + lq;
            const float* vsrc = Vbase + (size_t)(j0 + lr) * DIM + lq;
#pragma unroll
            for (int c = 0; c < 4; c++) {
                float4 f = *(const float4*)(ks + c * 4);
                int d = lq + c * 4;
                KPs[d + 0][lr] = f.x; KPs[d + 1][lr] = f.y;
                KPs[d + 2][lr] = f.z; KPs[d + 3][lr] = f.w;
            }
#pragma unroll
            for (int c = 0; c < 4; c++) {
                float4 f = *(const float4*)(vsrc + c * 4);
                *(float4*)&Vs[lr][lq + c * 4] = f;
            }
        }
        __syncthreads();

        // S = Q K^T (scaled)
        float s[4][4];
#pragma unroll
        for (int r = 0; r < 4; r++)
#pragma unroll
            for (int c = 0; c < 4; c++) s[r][c] = 0.f;
#pragma unroll
        for (int d = 0; d < 64; d++) {
            float4 qf = *(float4*)&Qst[d][ty * 4];
            float4 kf = *(float4*)&KPs[d][tx * 4];
            float qa[4] = {qf.x, qf.y, qf.z, qf.w};
            float ka[4] = {kf.x, kf.y, kf.z, kf.w};
#pragma unroll
            for (int r = 0; r < 4; r++)
#pragma unroll
                for (int c = 0; c < 4; c++)
                    s[r][c] = fmaf(qa[r], ka[c], s[r][c]);
        }
        const float scale = 0.125f;  // 1/sqrt(64)
#pragma unroll
        for (int r = 0; r < 4; r++)
#pragma unroll
            for (int c = 0; c < 4; c++) s[r][c] *= scale;

        __syncthreads();   // everyone finished reading Kst before P overwrites

        // Online softmax per row; write P into KPs
#pragma unroll
        for (int r = 0; r < 4; r++) {
            float mx = fmaxf(fmaxf(s[r][0], s[r][1]), fmaxf(s[r][2], s[r][3]));
            mx = fmaxf(mx, __shfl_xor_sync(0xffffffffu, mx, 8));
            mx = fmaxf(mx, __shfl_xor_sync(0xffffffffu, mx, 4));
            mx = fmaxf(mx, __shfl_xor_sync(0xffffffffu, mx, 2));
            mx = fmaxf(mx, __shfl_xor_sync(0xffffffffu, mx, 1));
            float mn = fmaxf(m_prev[r], mx);
            float corr = __expf(m_prev[r] - mn);
            float ps = 0.f;
#pragma unroll
            for (int c = 0; c < 4; c++) {
                s[r][c] = __expf(s[r][c] - mn);
                ps += s[r][c];
            }
            ps += __shfl_xor_sync(0xffffffffu, ps, 8);
            ps += __shfl_xor_sync(0xffffffffu, ps, 4);
            ps += __shfl_xor_sync(0xffffffffu, ps, 2);
            ps += __shfl_xor_sync(0xffffffffu, ps, 1);
            lsum[r] = lsum[r] * corr + ps;
            m_prev[r] = mn;
#pragma unroll
            for (int c = 0; c < 4; c++) O[r][c] *= corr;
            *(float4*)&KPs[ty * 4 + r][tx * 4] =
                make_float4(s[r][0], s[r][1], s[r][2], s[r][3]);
        }
        __syncthreads();

        // O += P @ V, chunked by 4 in jj: all-LDS128, 8 FFMA per LDS.
#pragma unroll 4
        for (int jj0 = 0; jj0 < 64; jj0 += 4) {
            float4 pf[4];
#pragma unroll
            for (int r = 0; r < 4; r++)
                pf[r] = *(float4*)&KPs[ty * 4 + r][jj0];
            float4 vf[4];
#pragma unroll
            for (int i = 0; i < 4; i++)
                vf[i] = *(float4*)&Vs[jj0 + i][tx * 4];
#pragma unroll
            for (int r = 0; r < 4; r++) {
                float pa[4] = {pf[r].x, pf[r].y, pf[r].z, pf[r].w};
#pragma unroll
                for (int i = 0; i < 4; i++) {
                    O[r][0] = fmaf(pa[i], vf[i].x, O[r][0]);
                    O[r][1] = fmaf(pa[i], vf[i].y, O[r][1]);
                    O[r][2] = fmaf(pa[i], vf[i].z, O[r][2]);
                    O[r][3] = fmaf(pa[i], vf[i].w, O[r][3]);
                }
            }
        }
    }

    // Write normalized output tile
    float* outp = g_AO + headOff + (size_t)(qt * 64) * DIM;
#pragma unroll
    for (int r = 0; r < 4; r++) {
        float inv = 1.f / lsum[r];
        float4 v = make_float4(O[r][0] * inv, O[r][1] * inv,
                               O[r][2] * inv, O[r][3] * inv);
        *(float4*)&outp[(size_t)(ty * 4 + r) * DIM + tx * 4] = v;
    }
}

// ---------------------------------------------------------------------------
// Mean over T (split + reduce), then output projection on [B, D] only.
// ---------------------------------------------------------------------------
__global__ void mean_partial()
{
    const int d  = blockIdx.x * 128 + threadIdx.x;
    const int tc = blockIdx.y;
    const int b  = blockIdx.z;
    const float* p = g_AO + ((size_t)(b * SEQ + tc * 128)) * DIM + d;
    float s = 0.f;
#pragma unroll 8
    for (int t = 0; t < 128; t++) s += p[(size_t)t * DIM];
    g_part[(tc * BATCH + b) * DIM + d] = s;
}

__global__ void mean_reduce()
{
    const int i = blockIdx.x * 256 + threadIdx.x;
    float s = 0.f;
#pragma unroll
    for (int tc = 0; tc < 16; tc++) s += g_part[tc * (BATCH * DIM) + i];
    g_mean[i] = s * (1.f / (float)SEQ);
}

__global__ void out_proj(const float* __restrict__ Wo,
                         const float* __restrict__ bo,
                         float* __restrict__ out)
{
    const int warp = threadIdx.x >> 5;
    const int lane = threadIdx.x & 31;
    const int idx = blockIdx.x * 8 + warp;
    const int b = idx >> 10;
    const int d = idx & 1023;
    const float* m = g_mean + b * DIM;
    const float* w = Wo + (size_t)d * DIM;
    float s = 0.f;
    for (int k = lane; k < DIM; k += 32) s = fmaf(m[k], w[k], s);
#pragma unroll
    for (int off = 16; off > 0; off >>= 1)
        s += __shfl_xor_sync(0xffffffffu, s, off);
    if (lane == 0) out[idx] = s + bo[d];
}

// ---------------------------------------------------------------------------
extern "C" void kernel_launch(void* const* d_in, const int* in_sizes, int n_in,
                              void* d_out, int out_size)
{
    const float* x  = (const float*)d_in[0];
    const float* Wq = (const float*)d_in[1];
    const float* bq = (const float*)d_in[2];
    const float* Wk = (const float*)d_in[3];
    const float* bk = (const float*)d_in[4];
    const float* Wv = (const float*)d_in[5];
    const float* bv = (const float*)d_in[6];
    const float* Wo = (const float*)d_in[7];
    const float* bo = (const float*)d_in[8];
    float* out = (float*)d_out;

    split_x<<<(ROWS * DIM / 4) / 256, 256>>>(x);
    split_w<<<dim3((DIM * DIM / 4) / 256, 3), 256>>>(Wq, Wk, Wv);
    qkv_gemm_mma<<<dim3(DIM / BN, ROWS / BM, 3), 256>>>(bq, bk, bv);
    attn_kernel<<<dim3(SEQ / 64, HEADS, BATCH), 256>>>();
    mean_partial<<<dim3(DIM / 128, 16, BATCH), 128>>>();
    mean_reduce<<<(BATCH * DIM) / 256, 256>>>();
    out_proj<<<(BATCH * DIM) / 8, 256>>>(Wo, bo, out);
}

// round 17
// speedup vs baseline: 1.9258x; 1.5585x over previous
#include <cuda_runtime.h>
#include <cuda_bf16.h>
#include <math.h>
#include <stdint.h>

// Problem constants
#define BATCH 4
#define SEQ   2048
#define DIM   1024
#define HEADS 16
#define HDIM  64
#define ROWS  (BATCH * SEQ)   // 8192

// QKV GEMM tiling
#define BM 128
#define BN 128
#define BK 32
#define BKP 40   // padded row stride (bf16): conflict-free frag loads

// Attention smem stride (bf16 elems): 72 -> frag LDS conflict-free
#define ATS 72

// Scratch (device globals; no allocation allowed)
__device__ float g_Q[ROWS * DIM];
__device__ float g_K[ROWS * DIM];
__device__ float g_V[ROWS * DIM];
__device__ float g_AO[ROWS * DIM];
__device__ float g_part[16 * BATCH * DIM];
__device__ float g_mean[BATCH * DIM];

__device__ __nv_bfloat16 g_xhi[ROWS * DIM];
__device__ __nv_bfloat16 g_xlo[ROWS * DIM];
__device__ __nv_bfloat16 g_Whi[3 * DIM * DIM];
__device__ __nv_bfloat16 g_Wlo[3 * DIM * DIM];

__device__ __forceinline__ uint32_t f2_to_bf2(float x, float y)
{
    __nv_bfloat162 t = __floats2bfloat162_rn(x, y);
    return *(uint32_t*)&t;
}

#define MMA_BF16(d, a, b) \
    asm volatile( \
        "mma.sync.aligned.m16n8k16.row.col.f32.bf16.bf16.f32 " \
        "{%0,%1,%2,%3}, {%4,%5,%6,%7}, {%8,%9}, {%0,%1,%2,%3};\n" \
        : "+f"(d[0]), "+f"(d[1]), "+f"(d[2]), "+f"(d[3]) \
        : "r"(a[0]), "r"(a[1]), "r"(a[2]), "r"(a[3]), "r"(b[0]), "r"(b[1]))

// ---------------------------------------------------------------------------
// fp32 -> bf16 hi/lo split converters
// ---------------------------------------------------------------------------
__global__ void split_x(const float* __restrict__ src)
{
    const int idx = blockIdx.x * blockDim.x + threadIdx.x;  // float4 index
    float4 v = ((const float4*)src)[idx];
    float h0 = __bfloat162float(__float2bfloat16_rn(v.x));
    float h1 = __bfloat162float(__float2bfloat16_rn(v.y));
    float h2 = __bfloat162float(__float2bfloat16_rn(v.z));
    float h3 = __bfloat162float(__float2bfloat16_rn(v.w));
    ((uint32_t*)g_xhi)[idx * 2 + 0] = f2_to_bf2(h0, h1);
    ((uint32_t*)g_xhi)[idx * 2 + 1] = f2_to_bf2(h2, h3);
    ((uint32_t*)g_xlo)[idx * 2 + 0] = f2_to_bf2(v.x - h0, v.y - h1);
    ((uint32_t*)g_xlo)[idx * 2 + 1] = f2_to_bf2(v.z - h2, v.w - h3);
}

__global__ void split_w(const float* __restrict__ Wq,
                        const float* __restrict__ Wk,
                        const float* __restrict__ Wv)
{
    const int z = blockIdx.y;
    const float* src = (z == 0) ? Wq : (z == 1) ? Wk : Wv;
    const int idx = blockIdx.x * blockDim.x + threadIdx.x;
    const size_t base2 = (size_t)z * (DIM * DIM / 2);
    float4 v = ((const float4*)src)[idx];
    float h0 = __bfloat162float(__float2bfloat16_rn(v.x));
    float h1 = __bfloat162float(__float2bfloat16_rn(v.y));
    float h2 = __bfloat162float(__float2bfloat16_rn(v.z));
    float h3 = __bfloat162float(__float2bfloat16_rn(v.w));
    ((uint32_t*)g_Whi)[base2 + idx * 2 + 0] = f2_to_bf2(h0, h1);
    ((uint32_t*)g_Whi)[base2 + idx * 2 + 1] = f2_to_bf2(h2, h3);
    ((uint32_t*)g_Wlo)[base2 + idx * 2 + 0] = f2_to_bf2(v.x - h0, v.y - h1);
    ((uint32_t*)g_Wlo)[base2 + idx * 2 + 1] = f2_to_bf2(v.z - h2, v.w - h3);
}

// ---------------------------------------------------------------------------
// QKV projection with bf16 split-precision tensor-core MMA. (verified R5)
// ---------------------------------------------------------------------------
__global__ __launch_bounds__(256) void qkv_gemm_mma(
    const float* __restrict__ bq,
    const float* __restrict__ bk,
    const float* __restrict__ bv)
{
    const int z = blockIdx.z;
    const float* bias;
    float* out;
    if (z == 0)      { bias = bq; out = g_Q; }
    else if (z == 1) { bias = bk; out = g_K; }
    else             { bias = bv; out = g_V; }

    const __nv_bfloat16* Bhi = g_Whi + (size_t)z * DIM * DIM;
    const __nv_bfloat16* Blo = g_Wlo + (size_t)z * DIM * DIM;

    __shared__ __nv_bfloat16 sAhi[BM * BKP];
    __shared__ __nv_bfloat16 sAlo[BM * BKP];
    __shared__ __nv_bfloat16 sBhi[BN * BKP];
    __shared__ __nv_bfloat16 sBlo[BN * BKP];

    const int tid = threadIdx.x;
    const int wid = tid >> 5;
    const int lane = tid & 31;
    const int warp_m = wid & 1;
    const int warp_n = wid >> 1;
    const int g = lane >> 2;
    const int tg = (lane & 3) * 2;

    const int row0 = blockIdx.y * BM;
    const int col0 = blockIdx.x * BN;

    const int lrow = tid >> 2;
    const int lcol = (tid & 3) * 8;

    const __nv_bfloat16* gA0hi = &g_xhi[(size_t)(row0 + lrow) * DIM + lcol];
    const __nv_bfloat16* gA1hi = &g_xhi[(size_t)(row0 + lrow + 64) * DIM + lcol];
    const __nv_bfloat16* gA0lo = &g_xlo[(size_t)(row0 + lrow) * DIM + lcol];
    const __nv_bfloat16* gA1lo = &g_xlo[(size_t)(row0 + lrow + 64) * DIM + lcol];
    const __nv_bfloat16* gB0hi = &Bhi[(size_t)(col0 + lrow) * DIM + lcol];
    const __nv_bfloat16* gB1hi = &Bhi[(size_t)(col0 + lrow + 64) * DIM + lcol];
    const __nv_bfloat16* gB0lo = &Blo[(size_t)(col0 + lrow) * DIM + lcol];
    const __nv_bfloat16* gB1lo = &Blo[(size_t)(col0 + lrow + 64) * DIM + lcol];

    float acc[4][4][4];
#pragma unroll
    for (int mf = 0; mf < 4; mf++)
#pragma unroll
        for (int nf = 0; nf < 4; nf++)
#pragma unroll
            for (int i = 0; i < 4; i++) acc[mf][nf][i] = 0.f;

    uint4 pA0hi, pA1hi, pA0lo, pA1lo, pB0hi, pB1hi, pB0lo, pB1lo;

    pA0hi = *(const uint4*)(gA0hi); pA1hi = *(const uint4*)(gA1hi);
    pA0lo = *(const uint4*)(gA0lo); pA1lo = *(const uint4*)(gA1lo);
    pB0hi = *(const uint4*)(gB0hi); pB1hi = *(const uint4*)(gB1hi);
    pB0lo = *(const uint4*)(gB0lo); pB1lo = *(const uint4*)(gB1lo);

    for (int k0 = 0; k0 < DIM; k0 += BK) {
        *(uint4*)&sAhi[lrow * BKP + lcol] = pA0hi;
        *(uint4*)&sAhi[(lrow + 64) * BKP + lcol] = pA1hi;
        *(uint4*)&sAlo[lrow * BKP + lcol] = pA0lo;
        *(uint4*)&sAlo[(lrow + 64) * BKP + lcol] = pA1lo;
        *(uint4*)&sBhi[lrow * BKP + lcol] = pB0hi;
        *(uint4*)&sBhi[(lrow + 64) * BKP + lcol] = pB1hi;
        *(uint4*)&sBlo[lrow * BKP + lcol] = pB0lo;
        *(uint4*)&sBlo[(lrow + 64) * BKP + lcol] = pB1lo;
        __syncthreads();

        if (k0 + BK < DIM) {
            const int kn = k0 + BK;
            pA0hi = *(const uint4*)(gA0hi + kn); pA1hi = *(const uint4*)(gA1hi + kn);
            pA0lo = *(const uint4*)(gA0lo + kn); pA1lo = *(const uint4*)(gA1lo + kn);
            pB0hi = *(const uint4*)(gB0hi + kn); pB1hi = *(const uint4*)(gB1hi + kn);
            pB0lo = *(const uint4*)(gB0lo + kn); pB1lo = *(const uint4*)(gB1lo + kn);
        }

#pragma unroll
        for (int ks = 0; ks < BK; ks += 16) {
            uint32_t ahi[4][4], alo[4][4], bhi[4][2], blo[4][2];
#pragma unroll
            for (int mf = 0; mf < 4; mf++) {
                const int am = warp_m * 64 + mf * 16 + g;
                ahi[mf][0] = *(const uint32_t*)&sAhi[am * BKP + ks + tg];
                ahi[mf][1] = *(const uint32_t*)&sAhi[(am + 8) * BKP + ks + tg];
                ahi[mf][2] = *(const uint32_t*)&sAhi[am * BKP + ks + 8 + tg];
                ahi[mf][3] = *(const uint32_t*)&sAhi[(am + 8) * BKP + ks + 8 + tg];
                alo[mf][0] = *(const uint32_t*)&sAlo[am * BKP + ks + tg];
                alo[mf][1] = *(const uint32_t*)&sAlo[(am + 8) * BKP + ks + tg];
                alo[mf][2] = *(const uint32_t*)&sAlo[am * BKP + ks + 8 + tg];
                alo[mf][3] = *(const uint32_t*)&sAlo[(am + 8) * BKP + ks + 8 + tg];
            }
#pragma unroll
            for (int nf = 0; nf < 4; nf++) {
                const int bn = warp_n * 32 + nf * 8 + g;
                bhi[nf][0] = *(const uint32_t*)&sBhi[bn * BKP + ks + tg];
                bhi[nf][1] = *(const uint32_t*)&sBhi[bn * BKP + ks + 8 + tg];
                blo[nf][0] = *(const uint32_t*)&sBlo[bn * BKP + ks + tg];
                blo[nf][1] = *(const uint32_t*)&sBlo[bn * BKP + ks + 8 + tg];
            }
#pragma unroll
            for (int mf = 0; mf < 4; mf++)
#pragma unroll
                for (int nf = 0; nf < 4; nf++) {
                    MMA_BF16(acc[mf][nf], ahi[mf], bhi[nf]);
                    MMA_BF16(acc[mf][nf], ahi[mf], blo[nf]);
                    MMA_BF16(acc[mf][nf], alo[mf], bhi[nf]);
                }
        }
        __syncthreads();
    }

#pragma unroll
    for (int mf = 0; mf < 4; mf++) {
        const int r0 = row0 + warp_m * 64 + mf * 16 + g;
#pragma unroll
        for (int nf = 0; nf < 4; nf++) {
            const int c = col0 + warp_n * 32 + nf * 8 + tg;
            float2 v0 = make_float2(acc[mf][nf][0] + bias[c],
                                    acc[mf][nf][1] + bias[c + 1]);
            float2 v1 = make_float2(acc[mf][nf][2] + bias[c],
                                    acc[mf][nf][3] + bias[c + 1]);
            *(float2*)&out[(size_t)r0 * DIM + c] = v0;
            *(float2*)&out[(size_t)(r0 + 8) * DIM + c] = v1;
        }
    }
}

// ---------------------------------------------------------------------------
// Flash attention with bf16 split-precision tensor-core MMA.
// One CTA per (qtile=64, head, batch); 128 threads = 4 warps, 16 q-rows each.
// Q in registers (A-frags, hi/lo, scale folded); K/V^T staged in smem bf16.
// Softmax in accumulator registers; P rebuilt as A-frags from C-frags.
// ---------------------------------------------------------------------------
__global__ __launch_bounds__(128) void attn_mma()
{
    const int qt = blockIdx.x;   // 0..31
    const int h  = blockIdx.y;   // 0..15
    const int b  = blockIdx.z;   // 0..3

    __shared__ __align__(16) __nv_bfloat16 sKhi[64 * ATS];
    __shared__ __align__(16) __nv_bfloat16 sKlo[64 * ATS];
    __shared__ __align__(16) __nv_bfloat16 sVhi[64 * ATS];  // transposed [d][kv]
    __shared__ __align__(16) __nv_bfloat16 sVlo[64 * ATS];

    const int tid = threadIdx.x;
    const int wid = tid >> 5;
    const int lane = tid & 31;
    const int g = lane >> 2;          // 0..7
    const int qd = lane & 3;          // 0..3; tg = qd*2

    const size_t headOff = (size_t)b * SEQ * DIM + (size_t)h * HDIM;
    const int r0 = qt * 64 + wid * 16;

    // --- Load Q as A-frags (hi/lo), scale 1/8 folded in (exact) ---
    uint32_t qhi[4][4], qlo[4][4];
    {
        const float* Qb = g_Q + headOff;
#pragma unroll
        for (int kb = 0; kb < 4; kb++) {
#pragma unroll
            for (int half = 0; half < 2; half++) {
#pragma unroll
                for (int rr = 0; rr < 2; rr++) {
                    const int row = r0 + g + rr * 8;
                    float2 v = *(const float2*)&Qb[(size_t)row * DIM + kb * 16 + half * 8 + qd * 2];
                    v.x *= 0.125f; v.y *= 0.125f;
                    float hx = __bfloat162float(__float2bfloat16_rn(v.x));
                    float hy = __bfloat162float(__float2bfloat16_rn(v.y));
                    qhi[kb][half * 2 + rr] = f2_to_bf2(hx, hy);
                    qlo[kb][half * 2 + rr] = f2_to_bf2(v.x - hx, v.y - hy);
                }
            }
        }
    }

    float oacc[8][4];
#pragma unroll
    for (int nf = 0; nf < 8; nf++)
#pragma unroll
        for (int i = 0; i < 4; i++) oacc[nf][i] = 0.f;
    float mA = -INFINITY, mB = -INFINITY, lsA = 0.f, lsB = 0.f;

    const float* Kb = g_K + headOff;
    const float* Vb = g_V + headOff;

    for (int j0 = 0; j0 < SEQ; j0 += 64) {
        __syncthreads();
        // --- Stage K tile [kv][d] as bf16 hi/lo ---
        {
            const int row = tid >> 1;
            const int c0 = (tid & 1) * 32;
            const float* src = Kb + (size_t)(j0 + row) * DIM + c0;
#pragma unroll
            for (int c = 0; c < 32; c += 4) {
                float4 f = *(const float4*)(src + c);
                float h0 = __bfloat162float(__float2bfloat16_rn(f.x));
                float h1 = __bfloat162float(__float2bfloat16_rn(f.y));
                float h2 = __bfloat162float(__float2bfloat16_rn(f.z));
                float h3 = __bfloat162float(__float2bfloat16_rn(f.w));
                *(uint2*)&sKhi[row * ATS + c0 + c] =
                    make_uint2(f2_to_bf2(h0, h1), f2_to_bf2(h2, h3));
                *(uint2*)&sKlo[row * ATS + c0 + c] =
                    make_uint2(f2_to_bf2(f.x - h0, f.y - h1), f2_to_bf2(f.z - h2, f.w - h3));
            }
        }
        // --- Stage V tile transposed [d][kv] as bf16 hi/lo ---
        // Warp wid owns d-columns [wid*16, wid*16+16); lane owns kv pair
        // (2*lane, 2*lane+1).
        {
            const int cc0 = wid * 16;              // d cols for this warp
            const float* v0 = Vb + (size_t)(j0 + 2 * lane) * DIM + cc0;
            const float* v1 = v0 + DIM;
#pragma unroll
            for (int c = 0; c < 16; c += 4) {
                float4 a = *(const float4*)(v0 + c);
                float4 bb = *(const float4*)(v1 + c);
                const float av[4] = {a.x, a.y, a.z, a.w};
                const float bv[4] = {bb.x, bb.y, bb.z, bb.w};
#pragma unroll
                for (int e = 0; e < 4; e++) {
                    const int col = cc0 + c + e;
                    float ha = __bfloat162float(__float2bfloat16_rn(av[e]));
                    float hb = __bfloat162float(__float2bfloat16_rn(bv[e]));
                    *(uint32_t*)&sVhi[col * ATS + 2 * lane] = f2_to_bf2(ha, hb);
                    *(uint32_t*)&sVlo[col * ATS + 2 * lane] = f2_to_bf2(av[e] - ha, bv[e] - hb);
                }
            }
        }
        __syncthreads();

        // --- S = (Q*scale) K^T, 3-pass split ---
        float sacc[8][4];
#pragma unroll
        for (int nf = 0; nf < 8; nf++)
#pragma unroll
            for (int i = 0; i < 4; i++) sacc[nf][i] = 0.f;
#pragma unroll
        for (int nf = 0; nf < 8; nf++) {
#pragma unroll
            for (int kb = 0; kb < 4; kb++) {
                const int base = (nf * 8 + g) * ATS + kb * 16 + qd * 2;
                uint32_t bh[2], bl[2];
                bh[0] = *(const uint32_t*)&sKhi[base];
                bh[1] = *(const uint32_t*)&sKhi[base + 8];
                bl[0] = *(const uint32_t*)&sKlo[base];
                bl[1] = *(const uint32_t*)&sKlo[base + 8];
                MMA_BF16(sacc[nf], qhi[kb], bh);
                MMA_BF16(sacc[nf], qlo[kb], bh);
                MMA_BF16(sacc[nf], qhi[kb], bl);
            }
        }

        // --- Online softmax in registers (rows g and g+8) ---
        float mxA = -INFINITY, mxB = -INFINITY;
#pragma unroll
        for (int nf = 0; nf < 8; nf++) {
            mxA = fmaxf(mxA, fmaxf(sacc[nf][0], sacc[nf][1]));
            mxB = fmaxf(mxB, fmaxf(sacc[nf][2], sacc[nf][3]));
        }
        mxA = fmaxf(mxA, __shfl_xor_sync(0xffffffffu, mxA, 1));
        mxA = fmaxf(mxA, __shfl_xor_sync(0xffffffffu, mxA, 2));
        mxB = fmaxf(mxB, __shfl_xor_sync(0xffffffffu, mxB, 1));
        mxB = fmaxf(mxB, __shfl_xor_sync(0xffffffffu, mxB, 2));

        const float mnA = fmaxf(mA, mxA);
        const float mnB = fmaxf(mB, mxB);
        const float cA = __expf(mA - mnA);
        const float cB = __expf(mB - mnB);
        mA = mnA; mB = mnB;

        float psA = 0.f, psB = 0.f;
#pragma unroll
        for (int nf = 0; nf < 8; nf++) {
            sacc[nf][0] = __expf(sacc[nf][0] - mnA);
            sacc[nf][1] = __expf(sacc[nf][1] - mnA);
            sacc[nf][2] = __expf(sacc[nf][2] - mnB);
            sacc[nf][3] = __expf(sacc[nf][3] - mnB);
            psA += sacc[nf][0] + sacc[nf][1];
            psB += sacc[nf][2] + sacc[nf][3];
        }
        psA += __shfl_xor_sync(0xffffffffu, psA, 1);
        psA += __shfl_xor_sync(0xffffffffu, psA, 2);
        psB += __shfl_xor_sync(0xffffffffu, psB, 1);
        psB += __shfl_xor_sync(0xffffffffu, psB, 2);
        lsA = lsA * cA + psA;
        lsB = lsB * cB + psB;
#pragma unroll
        for (int nf = 0; nf < 8; nf++) {
            oacc[nf][0] *= cA; oacc[nf][1] *= cA;
            oacc[nf][2] *= cB; oacc[nf][3] *= cB;
        }

        // --- O += P V, P as A-frags from C-frags, 3-pass split ---
#pragma unroll
        for (int kb = 0; kb < 4; kb++) {
            const float* pA = sacc[2 * kb];
            const float* pB = sacc[2 * kb + 1];
            uint32_t ph[4], pl[4];
            {
                float h0 = __bfloat162float(__float2bfloat16_rn(pA[0]));
                float h1 = __bfloat162float(__float2bfloat16_rn(pA[1]));
                ph[0] = f2_to_bf2(h0, h1); pl[0] = f2_to_bf2(pA[0] - h0, pA[1] - h1);
                float h2 = __bfloat162float(__float2bfloat16_rn(pA[2]));
                float h3 = __bfloat162float(__float2bfloat16_rn(pA[3]));
                ph[1] = f2_to_bf2(h2, h3); pl[1] = f2_to_bf2(pA[2] - h2, pA[3] - h3);
                float h4 = __bfloat162float(__float2bfloat16_rn(pB[0]));
                float h5 = __bfloat162float(__float2bfloat16_rn(pB[1]));
                ph[2] = f2_to_bf2(h4, h5); pl[2] = f2_to_bf2(pB[0] - h4, pB[1] - h5);
                float h6 = __bfloat162float(__float2bfloat16_rn(pB[2]));
                float h7 = __bfloat162float(__float2bfloat16_rn(pB[3]));
                ph[3] = f2_to_bf2(h6, h7); pl[3] = f2_to_bf2(pB[2] - h6, pB[3] - h7);
            }
#pragma unroll
            for (int nf = 0; nf < 8; nf++) {
                const int base = (nf * 8 + g) * ATS + kb * 16 + qd * 2;
                uint32_t bh[2], bl[2];
                bh[0] = *(const uint32_t*)&sVhi[base];
                bh[1] = *(const uint32_t*)&sVhi[base + 8];
                bl[0] = *(const uint32_t*)&sVlo[base];
                bl[1] = *(const uint32_t*)&sVlo[base + 8];
                MMA_BF16(oacc[nf], ph, bh);
                MMA_BF16(oacc[nf], pl, bh);
                MMA_BF16(oacc[nf], ph, bl);
            }
        }
    }

    // --- Normalize and write output tile ---
    const float invA = 1.f / lsA;
    const float invB = 1.f / lsB;
    float* outp = g_AO + headOff;
#pragma unroll
    for (int nf = 0; nf < 8; nf++) {
        const int c = nf * 8 + qd * 2;
        float2 v0 = make_float2(oacc[nf][0] * invA, oacc[nf][1] * invA);
        float2 v1 = make_float2(oacc[nf][2] * invB, oacc[nf][3] * invB);
        *(float2*)&outp[(size_t)(r0 + g) * DIM + c] = v0;
        *(float2*)&outp[(size_t)(r0 + g + 8) * DIM + c] = v1;
    }
}

// ---------------------------------------------------------------------------
// Mean over T (split + reduce), then output projection on [B, D] only.
// ---------------------------------------------------------------------------
__global__ void mean_partial()
{
    const int d  = blockIdx.x * 128 + threadIdx.x;
    const int tc = blockIdx.y;
    const int b  = blockIdx.z;
    const float* p = g_AO + ((size_t)(b * SEQ + tc * 128)) * DIM + d;
    float s = 0.f;
#pragma unroll 8
    for (int t = 0; t < 128; t++) s += p[(size_t)t * DIM];
    g_part[(tc * BATCH + b) * DIM + d] = s;
}

__global__ void mean_reduce()
{
    const int i = blockIdx.x * 256 + threadIdx.x;
    float s = 0.f;
#pragma unroll
    for (int tc = 0; tc < 16; tc++) s += g_part[tc * (BATCH * DIM) + i];
    g_mean[i] = s * (1.f / (float)SEQ);
}

__global__ void out_proj(const float* __restrict__ Wo,
                         const float* __restrict__ bo,
                         float* __restrict__ out)
{
    const int warp = threadIdx.x >> 5;
    const int lane = threadIdx.x & 31;
    const int idx = blockIdx.x * 8 + warp;
    const int b = idx >> 10;
    const int d = idx & 1023;
    const float* m = g_mean + b * DIM;
    const float* w = Wo + (size_t)d * DIM;
    float s = 0.f;
    for (int k = lane; k < DIM; k += 32) s = fmaf(m[k], w[k], s);
#pragma unroll
    for (int off = 16; off > 0; off >>= 1)
        s += __shfl_xor_sync(0xffffffffu, s, off);
    if (lane == 0) out[idx] = s + bo[d];
}

// ---------------------------------------------------------------------------
extern "C" void kernel_launch(void* const* d_in, const int* in_sizes, int n_in,
                              void* d_out, int out_size)
{
    const float* x  = (const float*)d_in[0];
    const float* Wq = (const float*)d_in[1];
    const float* bq = (const float*)d_in[2];
    const float* Wk = (const float*)d_in[3];
    const float* bk = (const float*)d_in[4];
    const float* Wv = (const float*)d_in[5];
    const float* bv = (const float*)d_in[6];
    const float* Wo = (const float*)d_in[7];
    const float* bo = (const float*)d_in[8];
    float* out = (float*)d_out;

    split_x<<<(ROWS * DIM / 4) / 256, 256>>>(x);
    split_w<<<dim3((DIM * DIM / 4) / 256, 3), 256>>>(Wq, Wk, Wv);
    qkv_gemm_mma<<<dim3(DIM / BN, ROWS / BM, 3), 256>>>(bq, bk, bv);
    attn_mma<<<dim3(SEQ / 64, HEADS, BATCH), 128>>>();
    mean_partial<<<dim3(DIM / 128, 16, BATCH), 128>>>();
    mean_reduce<<<(BATCH * DIM) / 256, 256>>>();
    out_proj<<<(BATCH * DIM) / 8, 256>>>(Wo, bo, out);
}